// round 16
// baseline (speedup 1.0000x reference)
#include <cuda_runtime.h>
#include <cuda_bf16.h>
#include <cstdint>

#define NN 50000
#define EE 400000
#define FF 128
#define RBFN 100
// packed-K hi/lo layouts: K=128 -> [hi|lo|hi] = 384 ; K=100 -> [hi|lo|hi|pad20] = 320
#define KP128 384
#define KP100 320

// ---------------- scratch (static device allocations; no cudaMalloc) ----------------
__device__ float g_qkv[(size_t)NN * 640];        // [q(128) | k(128) | v(384)]
__device__ float g_vp[(size_t)NN * 3 * 384];
__device__ float g_dkdv[(size_t)EE * 512];       // [dk(128) | dv(384)]
__device__ float g_xagg[(size_t)NN * FF];
__device__ float g_vagg[(size_t)NN * 384];
__device__ float g_o[(size_t)NN * 384];
__device__ float g_bqkv[640];
__device__ float g_bdkv[512];
__device__ int   g_hist[NN];
__device__ int   g_cursor[NN];
__device__ int   g_perm[EE];
// packed-K bf16 buffers
__device__ __nv_bfloat16 g_xn2[(size_t)NN * KP128];
__device__ __nv_bfloat16 g_vec2[(size_t)3 * NN * KP128];
__device__ __nv_bfloat16 g_fij2[(size_t)EE * KP100];
__device__ __nv_bfloat16 g_xagg2[(size_t)NN * KP128];
__device__ __nv_bfloat16 g_Wqkv2[640 * KP128];
__device__ __nv_bfloat16 g_Wvec2[384 * KP128];
__device__ __nv_bfloat16 g_Wdkv2[512 * KP100];
__device__ __nv_bfloat16 g_Wo2[384 * KP128];

// ---------------- helpers ----------------
__device__ __forceinline__ uint32_t smem_u32(const void* p) {
    uint32_t a;
    asm("{ .reg .u64 t; cvta.to.shared.u64 t, %1; cvt.u32.u64 %0, t; }" : "=r"(a) : "l"(p));
    return a;
}
__device__ __forceinline__ void cp_async16(uint32_t dst, const void* src, uint32_t src_bytes) {
    asm volatile("cp.async.cg.shared.global [%0], [%1], 16, %2;"
                 :: "r"(dst), "l"(src), "r"(src_bytes) : "memory");
}
#define CP_COMMIT() asm volatile("cp.async.commit_group;" ::: "memory")
#define CP_WAIT1()  asm volatile("cp.async.wait_group 1;" ::: "memory")

__device__ __forceinline__ void ldm_x4(uint32_t& r0, uint32_t& r1, uint32_t& r2, uint32_t& r3,
                                       uint32_t addr) {
    asm volatile("ldmatrix.sync.aligned.m8n8.x4.shared.b16 {%0,%1,%2,%3}, [%4];"
                 : "=r"(r0), "=r"(r1), "=r"(r2), "=r"(r3) : "r"(addr));
}
__device__ __forceinline__ void mma_bf16(float* c, const uint32_t* a, const uint32_t* b) {
    asm volatile("mma.sync.aligned.m16n8k16.row.col.f32.bf16.bf16.f32 "
                 "{%0,%1,%2,%3}, {%4,%5,%6,%7}, {%8,%9}, {%0,%1,%2,%3};"
                 : "+f"(c[0]), "+f"(c[1]), "+f"(c[2]), "+f"(c[3])
                 : "r"(a[0]), "r"(a[1]), "r"(a[2]), "r"(a[3]), "r"(b[0]), "r"(b[1]));
}
__device__ __forceinline__ void red_add_v4(float* p, float4 v) {
    asm volatile("red.global.add.v4.f32 [%0], {%1, %2, %3, %4};"
                 :: "l"(p), "f"(v.x), "f"(v.y), "f"(v.z), "f"(v.w) : "memory");
}
__device__ __forceinline__ uint32_t pack_bf16x2(float a, float b) {
    __nv_bfloat162 t = __floats2bfloat162_rn(a, b);
    return *(uint32_t*)&t;
}
__device__ __forceinline__ float bf_hi(float v) { return __bfloat162float(__float2bfloat16(v)); }

// ---------------- fused weight prep: concat + packed hi/lo (B layout: hi|hi|lo) -------
__global__ void prep_all(const float* __restrict__ Wq, const float* __restrict__ Wk,
                         const float* __restrict__ Wv, const float* __restrict__ bq,
                         const float* __restrict__ bk, const float* __restrict__ bv,
                         const float* __restrict__ Wdk, const float* __restrict__ Wdv,
                         const float* __restrict__ bdk, const float* __restrict__ bdv,
                         const float* __restrict__ Wvec, const float* __restrict__ Wo) {
    int i = blockIdx.x * blockDim.x + threadIdx.x;
    int r = i >> 7, c = i & 127;
    if (i < 640 * 128) {
        float v = (r < 128) ? Wq[r * 128 + c]
                : (r < 256) ? Wk[(r - 128) * 128 + c]
                            : Wv[(r - 256) * 128 + c];
        __nv_bfloat16 hi = __float2bfloat16(v);
        __nv_bfloat16 lo = __float2bfloat16(v - __bfloat162float(hi));
        g_Wqkv2[(size_t)r * KP128 + c] = hi;
        g_Wqkv2[(size_t)r * KP128 + 128 + c] = hi;
        g_Wqkv2[(size_t)r * KP128 + 256 + c] = lo;
    }
    if (i < 512 * 128) {
        if (c < RBFN) {
            float v = (r < 128) ? Wdk[r * RBFN + c] : Wdv[(r - 128) * RBFN + c];
            __nv_bfloat16 hi = __float2bfloat16(v);
            __nv_bfloat16 lo = __float2bfloat16(v - __bfloat162float(hi));
            g_Wdkv2[(size_t)r * KP100 + c] = hi;
            g_Wdkv2[(size_t)r * KP100 + 100 + c] = hi;
            g_Wdkv2[(size_t)r * KP100 + 200 + c] = lo;
        } else if (c < 120) {
            g_Wdkv2[(size_t)r * KP100 + 200 + c] = __float2bfloat16(0.f);  // cols 300-319
        }
    }
    if (i < 384 * 128) {
        {
            float v = Wvec[r * 128 + c];
            __nv_bfloat16 hi = __float2bfloat16(v);
            __nv_bfloat16 lo = __float2bfloat16(v - __bfloat162float(hi));
            g_Wvec2[(size_t)r * KP128 + c] = hi;
            g_Wvec2[(size_t)r * KP128 + 128 + c] = hi;
            g_Wvec2[(size_t)r * KP128 + 256 + c] = lo;
        }
        {
            float v = Wo[r * 128 + c];
            __nv_bfloat16 hi = __float2bfloat16(v);
            __nv_bfloat16 lo = __float2bfloat16(v - __bfloat162float(hi));
            g_Wo2[(size_t)r * KP128 + c] = hi;
            g_Wo2[(size_t)r * KP128 + 128 + c] = hi;
            g_Wo2[(size_t)r * KP128 + 256 + c] = lo;
        }
    }
    if (i < 640)
        g_bqkv[i] = (i < 128) ? bq[i] : (i < 256) ? bk[i - 128] : bv[i - 256];
    if (i < 512)
        g_bdkv[i] = (i < 128) ? bdk[i] : bdv[i - 128];
}

// ---------------- cvt K=128 (A layout: hi|lo|hi), warp-per-row ----------------
__global__ __launch_bounds__(256) void cvt128(const float* __restrict__ src,
                                              __nv_bfloat16* __restrict__ dst, int R) {
    int gw = (blockIdx.x * blockDim.x + threadIdx.x) >> 5;
    int lane = threadIdx.x & 31;
    if (gw >= R) return;
    float4 v = ((const float4*)(src + (size_t)gw * 128))[lane];
    float hx = bf_hi(v.x), hy = bf_hi(v.y), hz = bf_hi(v.z), hw = bf_hi(v.w);
    uint2 hi = make_uint2(pack_bf16x2(v.x, v.y), pack_bf16x2(v.z, v.w));
    uint2 lo = make_uint2(pack_bf16x2(v.x - hx, v.y - hy), pack_bf16x2(v.z - hz, v.w - hw));
    uint2* o = (uint2*)(dst + (size_t)gw * KP128);
    o[lane] = hi;
    o[32 + lane] = lo;
    o[64 + lane] = hi;
}

// ---------------- cvt K=100 (f_ij; A layout: hi|lo|hi|pad), warp-per-row ----------------
__global__ __launch_bounds__(256) void cvt100(const float* __restrict__ src,
                                              __nv_bfloat16* __restrict__ dst, int R) {
    int gw = (blockIdx.x * blockDim.x + threadIdx.x) >> 5;
    int lane = threadIdx.x & 31;
    if (gw >= R) return;
    uint2* o = (uint2*)(dst + (size_t)gw * KP100);
    if (lane < 25) {
        float4 v = *(const float4*)(src + (size_t)gw * 100 + lane * 4);
        float hx = bf_hi(v.x), hy = bf_hi(v.y), hz = bf_hi(v.z), hw = bf_hi(v.w);
        uint2 hi = make_uint2(pack_bf16x2(v.x, v.y), pack_bf16x2(v.z, v.w));
        uint2 lo = make_uint2(pack_bf16x2(v.x - hx, v.y - hy), pack_bf16x2(v.z - hz, v.w - hw));
        o[lane] = hi;          // cols 0-99
        o[25 + lane] = lo;     // cols 100-199
        o[50 + lane] = hi;     // cols 200-299
    } else if (lane < 30) {
        o[50 + lane] = make_uint2(0u, 0u);  // cols 300-319 zero pad
    }
}

// ---------------- LayerNorm (fused packed hi/lo output) ----------------
__global__ void ln_kernel(const float* __restrict__ x, const float* __restrict__ w,
                          const float* __restrict__ b) {
    int n = blockIdx.x;
    int f = threadIdx.x;  // 128 threads
    float v = x[(size_t)n * FF + f];
    __shared__ float red1[4], red2[4];
    float s = v;
    #pragma unroll
    for (int o = 16; o > 0; o >>= 1) s += __shfl_xor_sync(0xffffffffu, s, o);
    if ((f & 31) == 0) red1[f >> 5] = s;
    __syncthreads();
    float mean = (red1[0] + red1[1] + red1[2] + red1[3]) * (1.0f / FF);
    float c = v - mean;
    float s2 = c * c;
    #pragma unroll
    for (int o = 16; o > 0; o >>= 1) s2 += __shfl_xor_sync(0xffffffffu, s2, o);
    if ((f & 31) == 0) red2[f >> 5] = s2;
    __syncthreads();
    float var = (red2[0] + red2[1] + red2[2] + red2[3]) * (1.0f / FF);
    float y = c * rsqrtf(var + 1e-5f) * w[f] + b[f];
    __nv_bfloat16 hi = __float2bfloat16(y);
    __nv_bfloat16 lo = __float2bfloat16(y - __bfloat162float(hi));
    g_xn2[(size_t)n * KP128 + f] = hi;
    g_xn2[(size_t)n * KP128 + 128 + f] = lo;
    g_xn2[(size_t)n * KP128 + 256 + f] = hi;
}

// ---------------- counting sort by dst ----------------
__global__ void hist_kernel(const int* __restrict__ ei) {
    int i = blockIdx.x * blockDim.x + threadIdx.x;
    if (i < EE) atomicAdd(&g_hist[ei[EE + i]], 1);
}
__global__ __launch_bounds__(1024) void scan_kernel() {
    __shared__ int wsum[32];
    __shared__ int carry;
    int tid = threadIdx.x, lane = tid & 31, wid = tid >> 5;
    if (tid == 0) carry = 0;
    __syncthreads();
    for (int c = 0; c < NN; c += 1024) {
        int idx = c + tid;
        int v = (idx < NN) ? g_hist[idx] : 0;
        int x = v;
        #pragma unroll
        for (int o = 1; o < 32; o <<= 1) {
            int t = __shfl_up_sync(0xffffffffu, x, o);
            if (lane >= o) x += t;
        }
        if (lane == 31) wsum[wid] = x;
        __syncthreads();
        if (wid == 0) {
            int s = wsum[lane];
            #pragma unroll
            for (int o = 1; o < 32; o <<= 1) {
                int t = __shfl_up_sync(0xffffffffu, s, o);
                if (lane >= o) s += t;
            }
            wsum[lane] = s;
        }
        __syncthreads();
        int excl = carry + (wid ? wsum[wid - 1] : 0) + x - v;
        if (idx < NN) g_cursor[idx] = excl;
        __syncthreads();
        if (tid == 0) carry += wsum[31];
        __syncthreads();
    }
}
__global__ void scatter_kernel(const int* __restrict__ ei) {
    int i = blockIdx.x * blockDim.x + threadIdx.x;
    if (i >= EE) return;
    int d = ei[EE + i];
    int pos = atomicAdd(&g_cursor[d], 1);
    g_perm[pos] = i;
}

// ---------------- HMMA bf16 GEMM v5: plain packed-K, 3-stage, 128x128 tile ----------
#define SPITCH 40
#define STAGE_BYTES (128 * SPITCH * 2)
#define HMMA_SMEM (3 * 2 * STAGE_BYTES)

__global__ __launch_bounds__(256, 2) void hmma_gemm(
    const __nv_bfloat16* __restrict__ A2, const __nv_bfloat16* __restrict__ B2,
    const float* __restrict__ bias, float* __restrict__ C, int M, int Nn, int act,
    int nkt) {
    extern __shared__ char dynsmem[];

    int tid = threadIdx.x;
    int wid = tid >> 5, lane = tid & 31;
    int wm = wid & 1, wn = wid >> 1;
    int row0 = blockIdx.y * 128;
    int col0 = blockIdx.x * 128;
    size_t KP = (size_t)nkt * 32;

    uint32_t sA_base[3], sB_base[3];
    #pragma unroll
    for (int s = 0; s < 3; s++) {
        sA_base[s] = smem_u32(dynsmem + s * 2 * STAGE_BYTES);
        sB_base[s] = sA_base[s] + STAGE_BYTES;
    }

    float acc[4][4][4];
    #pragma unroll
    for (int i = 0; i < 4; i++)
        #pragma unroll
        for (int j = 0; j < 4; j++)
            #pragma unroll
            for (int k = 0; k < 4; k++) acc[i][j][k] = 0.f;

    auto prefetch = [&](int kt) {
        int buf = kt % 3;
        int off = kt * 32;
        #pragma unroll
        for (int i = 0; i < 2; i++) {
            int idx = tid + i * 256;
            int r = idx >> 2;
            int ch = idx & 3;
            uint32_t soff = (uint32_t)(r * SPITCH + ch * 8) * 2;
            uint32_t valid = (row0 + r < M) ? 16u : 0u;
            cp_async16(sA_base[buf] + soff,
                       A2 + (size_t)(row0 + r) * KP + off + ch * 8, valid);
            cp_async16(sB_base[buf] + soff,
                       B2 + (size_t)(col0 + r) * KP + off + ch * 8, 16u);
        }
        CP_COMMIT();
    };

    prefetch(0);
    prefetch(1);
    #pragma unroll 1
    for (int kt = 0; kt < nkt; kt++) {
        CP_WAIT1();
        __syncthreads();
        if (kt + 2 < nkt) prefetch(kt + 2);
        else CP_COMMIT();
        int buf = kt % 3;
        #pragma unroll
        for (int ks = 0; ks < 32; ks += 16) {
            uint32_t a[4][4], b[4][2];
            #pragma unroll
            for (int mi = 0; mi < 4; mi++) {
                int r = wm * 64 + mi * 16 + (lane & 15);
                int c = ks + (lane >> 4) * 8;
                ldm_x4(a[mi][0], a[mi][1], a[mi][2], a[mi][3],
                       sA_base[buf] + (uint32_t)(r * SPITCH + c) * 2);
            }
            #pragma unroll
            for (int nip = 0; nip < 2; nip++) {
                int m = lane >> 3;
                int r = wn * 32 + nip * 16 + (m >> 1) * 8 + (lane & 7);
                int c = ks + (m & 1) * 8;
                ldm_x4(b[2 * nip][0], b[2 * nip][1], b[2 * nip + 1][0], b[2 * nip + 1][1],
                       sB_base[buf] + (uint32_t)(r * SPITCH + c) * 2);
            }
            #pragma unroll
            for (int mi = 0; mi < 4; mi++)
                #pragma unroll
                for (int ni = 0; ni < 4; ni++)
                    mma_bf16(acc[mi][ni], a[mi], b[ni]);
        }
    }

    #pragma unroll
    for (int ni = 0; ni < 4; ni++) {
        int n = col0 + wn * 32 + ni * 8 + (lane & 3) * 2;
        float b0 = bias[n], b1 = bias[n + 1];
        #pragma unroll
        for (int mi = 0; mi < 4; mi++) {
            int m = row0 + wm * 64 + mi * 16 + (lane >> 2);
            float v0 = acc[mi][ni][0] + b0;
            float v1 = acc[mi][ni][1] + b1;
            float v2 = acc[mi][ni][2] + b0;
            float v3 = acc[mi][ni][3] + b1;
            if (act) {
                v0 = v0 / (1.f + __expf(-v0));
                v1 = v1 / (1.f + __expf(-v1));
                v2 = v2 / (1.f + __expf(-v2));
                v3 = v3 / (1.f + __expf(-v3));
            }
            if (m < M)     *(float2*)(C + (size_t)m * Nn + n)       = make_float2(v0, v1);
            if (m + 8 < M) *(float2*)(C + (size_t)(m + 8) * Nn + n) = make_float2(v2, v3);
        }
    }
}

// ---------------- edge kernel v5b: dst-sorted, register accumulation, CHUNK=4 --------
#define CHUNK 4
__global__ __launch_bounds__(256) void edge_kernel(const int* __restrict__ ei,
                                                   const float* __restrict__ r_ij,
                                                   const float* __restrict__ d_ij,
                                                   const float* __restrict__ vec) {
    int gw = (blockIdx.x * blockDim.x + threadIdx.x) >> 5;
    int lane = threadIdx.x & 31;
    size_t base = (size_t)gw * CHUNK;
    if (base >= EE) return;
    int nmax = (int)(((size_t)EE - base) < CHUNK ? (EE - base) : CHUNK);

    int eL = 0, srcL = 0, dstL = -1;
    float rL = 0.f, dxL = 0.f, dyL = 0.f, dzL = 0.f;
    if (lane < nmax) {
        eL = g_perm[base + lane];
        srcL = ei[eL];
        dstL = ei[EE + eL];
        rL = r_ij[eL];
        dxL = d_ij[(size_t)eL * 3 + 0];
        dyL = d_ij[(size_t)eL * 3 + 1];
        dzL = d_ij[(size_t)eL * 3 + 2];
    }

    int h = lane >> 2;
    int d4 = (lane & 3) * 4;
    int prev = -1;
    float4 q = make_float4(0.f, 0.f, 0.f, 0.f);
    float4 ax  = make_float4(0.f, 0.f, 0.f, 0.f);
    float4 av0 = ax, av1 = ax, av2 = ax;

    for (int i = 0; i < nmax; i++) {
        int e   = __shfl_sync(0xffffffffu, eL, i);
        int src = __shfl_sync(0xffffffffu, srcL, i);
        int dst = __shfl_sync(0xffffffffu, dstL, i);
        if (dst != prev) {
            if (prev >= 0) {
                red_add_v4(g_xagg + (size_t)prev * FF + lane * 4, ax);
                red_add_v4(g_vagg + (size_t)prev * 384 +       lane * 4, av0);
                red_add_v4(g_vagg + (size_t)prev * 384 + 128 + lane * 4, av1);
                red_add_v4(g_vagg + (size_t)prev * 384 + 256 + lane * 4, av2);
            }
            ax = av0 = av1 = av2 = make_float4(0.f, 0.f, 0.f, 0.f);
            q = ((const float4*)(g_qkv + (size_t)dst * 640))[lane];
            prev = dst;
        }
        float4 kk = ((const float4*)(g_qkv + (size_t)src * 640 + 128))[lane];
        float4 dk = ((const float4*)(g_dkdv + (size_t)e * 512))[lane];
        float p = q.x * kk.x * dk.x + q.y * kk.y * dk.y + q.z * kk.z * dk.z + q.w * kk.w * dk.w;
        p += __shfl_xor_sync(0xffffffffu, p, 1);
        p += __shfl_xor_sync(0xffffffffu, p, 2);
        float attn = p / (1.f + __expf(-p));
        float r = __shfl_sync(0xffffffffu, rL, i);
        float cut = (r < 6.0f) ? 0.5f * (__cosf(r * 0.52359877559829887f) + 1.f) : 0.f;
        attn *= cut;

        const float* vb  = g_qkv  + (size_t)src * 640 + 256 + h * 48 + d4;
        const float* dvb = g_dkdv + (size_t)e * 512 + 128 + h * 48 + d4;
        float4 v0 = *(const float4*)vb;
        float4 v1 = *(const float4*)(vb + 16);
        float4 v2 = *(const float4*)(vb + 32);
        float4 w0 = *(const float4*)dvb;
        float4 w1 = *(const float4*)(dvb + 16);
        float4 w2 = *(const float4*)(dvb + 32);

        ax.x += v0.x * w0.x * attn; ax.y += v0.y * w0.y * attn;
        ax.z += v0.z * w0.z * attn; ax.w += v0.w * w0.w * attn;
        float4 v1m = make_float4(v1.x * w1.x, v1.y * w1.y, v1.z * w1.z, v1.w * w1.w);
        float4 v2m = make_float4(v2.x * w2.x, v2.y * w2.y, v2.z * w2.z, v2.w * w2.w);

        float dsx = __shfl_sync(0xffffffffu, dxL, i);
        float dsy = __shfl_sync(0xffffffffu, dyL, i);
        float dsz = __shfl_sync(0xffffffffu, dzL, i);
        float4 vv0 = ((const float4*)(vec + (size_t)src * 384))[lane];
        float4 vv1 = ((const float4*)(vec + (size_t)src * 384 + 128))[lane];
        float4 vv2 = ((const float4*)(vec + (size_t)src * 384 + 256))[lane];
        av0.x += vv0.x * v1m.x + v2m.x * dsx; av0.y += vv0.y * v1m.y + v2m.y * dsx;
        av0.z += vv0.z * v1m.z + v2m.z * dsx; av0.w += vv0.w * v1m.w + v2m.w * dsx;
        av1.x += vv1.x * v1m.x + v2m.x * dsy; av1.y += vv1.y * v1m.y + v2m.y * dsy;
        av1.z += vv1.z * v1m.z + v2m.z * dsy; av1.w += vv1.w * v1m.w + v2m.w * dsy;
        av2.x += vv2.x * v1m.x + v2m.x * dsz; av2.y += vv2.y * v1m.y + v2m.y * dsz;
        av2.z += vv2.z * v1m.z + v2m.z * dsz; av2.w += vv2.w * v1m.w + v2m.w * dsz;
    }
    if (prev >= 0) {
        red_add_v4(g_xagg + (size_t)prev * FF + lane * 4, ax);
        red_add_v4(g_vagg + (size_t)prev * 384 +       lane * 4, av0);
        red_add_v4(g_vagg + (size_t)prev * 384 + 128 + lane * 4, av1);
        red_add_v4(g_vagg + (size_t)prev * 384 + 256 + lane * 4, av2);
    }
}

// ---------------- final epilogue ----------------
__global__ void final_kernel(float* __restrict__ out) {
    int n = blockIdx.x;
    int f = threadIdx.x;  // 128
    size_t ob = (size_t)n * 384;
    float o1 = g_o[ob + f], o2 = g_o[ob + 128 + f], o3 = g_o[ob + 256 + f];
    size_t vb = (size_t)n * 1152;
    float vd = 0.f;
    #pragma unroll
    for (int s = 0; s < 3; s++)
        vd += g_vp[vb + s * 384 + f] * g_vp[vb + s * 384 + 128 + f];
    out[(size_t)n * FF + f] = vd * o2 + o3;
    #pragma unroll
    for (int s = 0; s < 3; s++) {
        float v3 = g_vp[vb + s * 384 + 256 + f];
        out[(size_t)NN * FF + ((size_t)n * 3 + s) * FF + f] =
            v3 * o1 + g_vagg[((size_t)n * 3 + s) * FF + f];
    }
}

// ---------------- launch: vp GEMM deferred to overlap with edge ----------------
extern "C" void kernel_launch(void* const* d_in, const int* in_sizes, int n_in,
                              void* d_out, int out_size) {
    const float* x    = (const float*)d_in[0];
    const float* vec  = (const float*)d_in[1];
    const int*   ei   = (const int*)d_in[2];
    const float* r_ij = (const float*)d_in[3];
    const float* f_ij = (const float*)d_in[4];
    const float* d_ij = (const float*)d_in[5];
    const float* ln_w = (const float*)d_in[6];
    const float* ln_b = (const float*)d_in[7];
    const float* Wq   = (const float*)d_in[8];
    const float* bq   = (const float*)d_in[9];
    const float* Wk   = (const float*)d_in[10];
    const float* bk   = (const float*)d_in[11];
    const float* Wv   = (const float*)d_in[12];
    const float* bv   = (const float*)d_in[13];
    const float* Wvec = (const float*)d_in[14];
    const float* bvec = (const float*)d_in[15];
    const float* Wo   = (const float*)d_in[16];
    const float* bo   = (const float*)d_in[17];
    const float* Wdk  = (const float*)d_in[18];
    const float* bdk  = (const float*)d_in[19];
    const float* Wdv  = (const float*)d_in[20];
    const float* bdv  = (const float*)d_in[21];
    float* out = (float*)d_out;

    void *pqkv, *pvp, *pdkdv, *pxagg, *pvagg, *po, *pbqkv, *pbdkv, *phist;
    void *pxn2, *pvec2, *pfij2, *pxagg2, *pWqkv2, *pWvec2, *pWdkv2, *pWo2;
    cudaGetSymbolAddress(&pqkv, g_qkv);
    cudaGetSymbolAddress(&pvp, g_vp);
    cudaGetSymbolAddress(&pdkdv, g_dkdv);
    cudaGetSymbolAddress(&pxagg, g_xagg);
    cudaGetSymbolAddress(&pvagg, g_vagg);
    cudaGetSymbolAddress(&po, g_o);
    cudaGetSymbolAddress(&pbqkv, g_bqkv);
    cudaGetSymbolAddress(&pbdkv, g_bdkv);
    cudaGetSymbolAddress(&phist, g_hist);
    cudaGetSymbolAddress(&pxn2, g_xn2);
    cudaGetSymbolAddress(&pvec2, g_vec2);
    cudaGetSymbolAddress(&pfij2, g_fij2);
    cudaGetSymbolAddress(&pxagg2, g_xagg2);
    cudaGetSymbolAddress(&pWqkv2, g_Wqkv2);
    cudaGetSymbolAddress(&pWvec2, g_Wvec2);
    cudaGetSymbolAddress(&pWdkv2, g_Wdkv2);
    cudaGetSymbolAddress(&pWo2, g_Wo2);

    cudaFuncSetAttribute(hmma_gemm, cudaFuncAttributeMaxDynamicSharedMemorySize, HMMA_SMEM);

    static cudaStream_t s1 = nullptr, s2 = nullptr;
    static cudaEvent_t ev0 = nullptr, evW = nullptr, evQ = nullptr, evS = nullptr,
                       evV = nullptr, evG = nullptr;
    if (!s1) {
        cudaStreamCreateWithFlags(&s1, cudaStreamNonBlocking);
        cudaStreamCreateWithFlags(&s2, cudaStreamNonBlocking);
        cudaEventCreateWithFlags(&ev0, cudaEventDisableTiming);
        cudaEventCreateWithFlags(&evW, cudaEventDisableTiming);
        cudaEventCreateWithFlags(&evQ, cudaEventDisableTiming);
        cudaEventCreateWithFlags(&evS, cudaEventDisableTiming);
        cudaEventCreateWithFlags(&evV, cudaEventDisableTiming);
        cudaEventCreateWithFlags(&evG, cudaEventDisableTiming);
    }
    cudaStream_t s0 = 0;  // capture-origin stream

    // ---- fork at capture start ----
    cudaEventRecord(ev0, s0);

    // ---- s0 (critical path): cvt100 -> (weights ready) dkdv GEMM ----
    cvt100<<<(EE * 32 + 255) / 256, 256, 0, s0>>>(f_ij, (__nv_bfloat16*)pfij2, EE);
    // ---- s1 (forked): prep -> ln -> qkv GEMM -> cvt(vec) [vp deferred] ----
    cudaStreamWaitEvent(s1, ev0, 0);
    prep_all<<<(640 * 128 + 255) / 256, 256, 0, s1>>>(Wq, Wk, Wv, bq, bk, bv,
                                                      Wdk, Wdv, bdk, bdv, Wvec, Wo);
    cudaEventRecord(evW, s1);                       // weights ready
    ln_kernel<<<NN, 128, 0, s1>>>(x, ln_w, ln_b);
    {
        dim3 grid(640 / 128, (NN + 127) / 128);
        hmma_gemm<<<grid, 256, HMMA_SMEM, s1>>>((const __nv_bfloat16*)pxn2,
                                                (const __nv_bfloat16*)pWqkv2,
                                                (const float*)pbqkv, (float*)pqkv,
                                                NN, 640, 0, 12);
    }
    cudaEventRecord(evQ, s1);                       // qkv ready (for edge)
    cvt128<<<(3 * NN * 32 + 255) / 256, 256, 0, s1>>>(vec, (__nv_bfloat16*)pvec2, 3 * NN);

    // ---- s2 (forked): counting sort + agg zeroing ----
    cudaStreamWaitEvent(s2, ev0, 0);
    cudaMemsetAsync(phist, 0, NN * sizeof(int), s2);
    hist_kernel<<<(EE + 255) / 256, 256, 0, s2>>>(ei);
    scan_kernel<<<1, 1024, 0, s2>>>();
    scatter_kernel<<<(EE + 255) / 256, 256, 0, s2>>>(ei);
    cudaMemsetAsync(pxagg, 0, (size_t)NN * FF * sizeof(float), s2);
    cudaMemsetAsync(pvagg, 0, (size_t)NN * 384 * sizeof(float), s2);
    cudaEventRecord(evS, s2);                       // sort + zeroed aggs ready

    // ---- s0: dkdv GEMM (after weights) [10 k-tiles] ----
    cudaStreamWaitEvent(s0, evW, 0);
    {
        dim3 grid(512 / 128, EE / 128);
        hmma_gemm<<<grid, 256, HMMA_SMEM, s0>>>((const __nv_bfloat16*)pfij2,
                                                (const __nv_bfloat16*)pWdkv2,
                                                (const float*)pbdkv, (float*)pdkdv,
                                                EE, 512, 1, 10);
    }
    cudaEventRecord(evG, s0);                       // dkdv done -> edge AND vp may start

    // ---- s1: vp GEMM deferred to overlap with edge (tensor vs LSU complementarity) ----
    cudaStreamWaitEvent(s1, evG, 0);
    {
        dim3 grid(384 / 128, (3 * NN + 127) / 128);
        hmma_gemm<<<grid, 256, HMMA_SMEM, s1>>>((const __nv_bfloat16*)pvec2,
                                                (const __nv_bfloat16*)pWvec2,
                                                bvec, (float*)pvp, 3 * NN, 384, 0, 12);
    }
    cudaEventRecord(evV, s1);                       // vp ready (for final)

    // ---- s0 join: edge -> cvt(xagg) -> o GEMM -> (join vp) final ----
    cudaStreamWaitEvent(s0, evQ, 0);
    cudaStreamWaitEvent(s0, evS, 0);
    {
        int warps = (EE + CHUNK - 1) / CHUNK;
        edge_kernel<<<(warps * 32 + 255) / 256, 256, 0, s0>>>(ei, r_ij, d_ij, vec);
    }
    cvt128<<<(NN * 32 + 255) / 256, 256, 0, s0>>>((const float*)pxagg,
                                                  (__nv_bfloat16*)pxagg2, NN);
    {
        dim3 grid(384 / 128, (NN + 127) / 128);
        hmma_gemm<<<grid, 256, HMMA_SMEM, s0>>>((const __nv_bfloat16*)pxagg2,
                                                (const __nv_bfloat16*)pWo2,
                                                bo, (float*)po, NN, 384, 0, 12);
    }
    cudaStreamWaitEvent(s0, evV, 0);
    final_kernel<<<NN, 128, 0, s0>>>(out);
}

// round 17
// speedup vs baseline: 1.0083x; 1.0083x over previous
#include <cuda_runtime.h>
#include <cuda_bf16.h>
#include <cstdint>

#define NN 50000
#define EE 400000
#define FF 128
#define RBFN 100
// packed-K hi/lo layouts: K=128 -> [hi|lo|hi] = 384 ; K=100 -> [hi|lo|hi|pad20] = 320
#define KP128 384
#define KP100 320

// ---------------- scratch (static device allocations; no cudaMalloc) ----------------
__device__ float g_qkv[(size_t)NN * 640];        // [q(128) | k(128) | v(384)]
__device__ float g_vp[(size_t)NN * 3 * 384];
__device__ float g_dkdv[(size_t)EE * 512];       // [dk(128) | dv(384)]
__device__ float g_xagg[(size_t)NN * FF];
__device__ float g_vagg[(size_t)NN * 384];
__device__ float g_o[(size_t)NN * 384];
__device__ float g_bqkv[640];
__device__ float g_bdkv[512];
__device__ int   g_hist[NN];
__device__ int   g_cursor[NN];
__device__ int   g_perm[EE];
// packed-K bf16 buffers
__device__ __nv_bfloat16 g_xn2[(size_t)NN * KP128];
__device__ __nv_bfloat16 g_vec2[(size_t)3 * NN * KP128];
__device__ __nv_bfloat16 g_fij2[(size_t)EE * KP100];
__device__ __nv_bfloat16 g_xagg2[(size_t)NN * KP128];
__device__ __nv_bfloat16 g_Wqkv2[640 * KP128];
__device__ __nv_bfloat16 g_Wvec2[384 * KP128];
__device__ __nv_bfloat16 g_Wdkv2[512 * KP100];
__device__ __nv_bfloat16 g_Wo2[384 * KP128];

// ---------------- helpers ----------------
__device__ __forceinline__ uint32_t smem_u32(const void* p) {
    uint32_t a;
    asm("{ .reg .u64 t; cvta.to.shared.u64 t, %1; cvt.u32.u64 %0, t; }" : "=r"(a) : "l"(p));
    return a;
}
__device__ __forceinline__ void cp_async16(uint32_t dst, const void* src, uint32_t src_bytes) {
    asm volatile("cp.async.cg.shared.global [%0], [%1], 16, %2;"
                 :: "r"(dst), "l"(src), "r"(src_bytes) : "memory");
}
#define CP_COMMIT() asm volatile("cp.async.commit_group;" ::: "memory")
#define CP_WAIT1()  asm volatile("cp.async.wait_group 1;" ::: "memory")

__device__ __forceinline__ void ldm_x4(uint32_t& r0, uint32_t& r1, uint32_t& r2, uint32_t& r3,
                                       uint32_t addr) {
    asm volatile("ldmatrix.sync.aligned.m8n8.x4.shared.b16 {%0,%1,%2,%3}, [%4];"
                 : "=r"(r0), "=r"(r1), "=r"(r2), "=r"(r3) : "r"(addr));
}
__device__ __forceinline__ void mma_bf16(float* c, const uint32_t* a, const uint32_t* b) {
    asm volatile("mma.sync.aligned.m16n8k16.row.col.f32.bf16.bf16.f32 "
                 "{%0,%1,%2,%3}, {%4,%5,%6,%7}, {%8,%9}, {%0,%1,%2,%3};"
                 : "+f"(c[0]), "+f"(c[1]), "+f"(c[2]), "+f"(c[3])
                 : "r"(a[0]), "r"(a[1]), "r"(a[2]), "r"(a[3]), "r"(b[0]), "r"(b[1]));
}
__device__ __forceinline__ void red_add_v4(float* p, float4 v) {
    asm volatile("red.global.add.v4.f32 [%0], {%1, %2, %3, %4};"
                 :: "l"(p), "f"(v.x), "f"(v.y), "f"(v.z), "f"(v.w) : "memory");
}
__device__ __forceinline__ uint32_t pack_bf16x2(float a, float b) {
    __nv_bfloat162 t = __floats2bfloat162_rn(a, b);
    return *(uint32_t*)&t;
}
__device__ __forceinline__ float bf_hi(float v) { return __bfloat162float(__float2bfloat16(v)); }

// ---------------- fused weight prep: concat + packed hi/lo (B layout: hi|hi|lo) -------
__global__ void prep_all(const float* __restrict__ Wq, const float* __restrict__ Wk,
                         const float* __restrict__ Wv, const float* __restrict__ bq,
                         const float* __restrict__ bk, const float* __restrict__ bv,
                         const float* __restrict__ Wdk, const float* __restrict__ Wdv,
                         const float* __restrict__ bdk, const float* __restrict__ bdv,
                         const float* __restrict__ Wvec, const float* __restrict__ Wo) {
    int i = blockIdx.x * blockDim.x + threadIdx.x;
    int r = i >> 7, c = i & 127;
    if (i < 640 * 128) {
        float v = (r < 128) ? Wq[r * 128 + c]
                : (r < 256) ? Wk[(r - 128) * 128 + c]
                            : Wv[(r - 256) * 128 + c];
        __nv_bfloat16 hi = __float2bfloat16(v);
        __nv_bfloat16 lo = __float2bfloat16(v - __bfloat162float(hi));
        g_Wqkv2[(size_t)r * KP128 + c] = hi;
        g_Wqkv2[(size_t)r * KP128 + 128 + c] = hi;
        g_Wqkv2[(size_t)r * KP128 + 256 + c] = lo;
    }
    if (i < 512 * 128) {
        if (c < RBFN) {
            float v = (r < 128) ? Wdk[r * RBFN + c] : Wdv[(r - 128) * RBFN + c];
            __nv_bfloat16 hi = __float2bfloat16(v);
            __nv_bfloat16 lo = __float2bfloat16(v - __bfloat162float(hi));
            g_Wdkv2[(size_t)r * KP100 + c] = hi;
            g_Wdkv2[(size_t)r * KP100 + 100 + c] = hi;
            g_Wdkv2[(size_t)r * KP100 + 200 + c] = lo;
        } else if (c < 120) {
            g_Wdkv2[(size_t)r * KP100 + 200 + c] = __float2bfloat16(0.f);  // cols 300-319
        }
    }
    if (i < 384 * 128) {
        {
            float v = Wvec[r * 128 + c];
            __nv_bfloat16 hi = __float2bfloat16(v);
            __nv_bfloat16 lo = __float2bfloat16(v - __bfloat162float(hi));
            g_Wvec2[(size_t)r * KP128 + c] = hi;
            g_Wvec2[(size_t)r * KP128 + 128 + c] = hi;
            g_Wvec2[(size_t)r * KP128 + 256 + c] = lo;
        }
        {
            float v = Wo[r * 128 + c];
            __nv_bfloat16 hi = __float2bfloat16(v);
            __nv_bfloat16 lo = __float2bfloat16(v - __bfloat162float(hi));
            g_Wo2[(size_t)r * KP128 + c] = hi;
            g_Wo2[(size_t)r * KP128 + 128 + c] = hi;
            g_Wo2[(size_t)r * KP128 + 256 + c] = lo;
        }
    }
    if (i < 640)
        g_bqkv[i] = (i < 128) ? bq[i] : (i < 256) ? bk[i - 128] : bv[i - 256];
    if (i < 512)
        g_bdkv[i] = (i < 128) ? bdk[i] : bdv[i - 128];
}

// ---------------- cvt K=128 (A layout: hi|lo|hi), warp-per-row ----------------
__global__ __launch_bounds__(256) void cvt128(const float* __restrict__ src,
                                              __nv_bfloat16* __restrict__ dst, int R) {
    int gw = (blockIdx.x * blockDim.x + threadIdx.x) >> 5;
    int lane = threadIdx.x & 31;
    if (gw >= R) return;
    float4 v = ((const float4*)(src + (size_t)gw * 128))[lane];
    float hx = bf_hi(v.x), hy = bf_hi(v.y), hz = bf_hi(v.z), hw = bf_hi(v.w);
    uint2 hi = make_uint2(pack_bf16x2(v.x, v.y), pack_bf16x2(v.z, v.w));
    uint2 lo = make_uint2(pack_bf16x2(v.x - hx, v.y - hy), pack_bf16x2(v.z - hz, v.w - hw));
    uint2* o = (uint2*)(dst + (size_t)gw * KP128);
    o[lane] = hi;
    o[32 + lane] = lo;
    o[64 + lane] = hi;
}

// ---------------- cvt K=100 (f_ij; A layout: hi|lo|hi|pad), warp-per-row ----------------
__global__ __launch_bounds__(256) void cvt100(const float* __restrict__ src,
                                              __nv_bfloat16* __restrict__ dst, int R) {
    int gw = (blockIdx.x * blockDim.x + threadIdx.x) >> 5;
    int lane = threadIdx.x & 31;
    if (gw >= R) return;
    uint2* o = (uint2*)(dst + (size_t)gw * KP100);
    if (lane < 25) {
        float4 v = *(const float4*)(src + (size_t)gw * 100 + lane * 4);
        float hx = bf_hi(v.x), hy = bf_hi(v.y), hz = bf_hi(v.z), hw = bf_hi(v.w);
        uint2 hi = make_uint2(pack_bf16x2(v.x, v.y), pack_bf16x2(v.z, v.w));
        uint2 lo = make_uint2(pack_bf16x2(v.x - hx, v.y - hy), pack_bf16x2(v.z - hz, v.w - hw));
        o[lane] = hi;          // cols 0-99
        o[25 + lane] = lo;     // cols 100-199
        o[50 + lane] = hi;     // cols 200-299
    } else if (lane < 30) {
        o[50 + lane] = make_uint2(0u, 0u);  // cols 300-319 zero pad
    }
}

// ---------------- LayerNorm (fused packed hi/lo output) ----------------
__global__ void ln_kernel(const float* __restrict__ x, const float* __restrict__ w,
                          const float* __restrict__ b) {
    int n = blockIdx.x;
    int f = threadIdx.x;  // 128 threads
    float v = x[(size_t)n * FF + f];
    __shared__ float red1[4], red2[4];
    float s = v;
    #pragma unroll
    for (int o = 16; o > 0; o >>= 1) s += __shfl_xor_sync(0xffffffffu, s, o);
    if ((f & 31) == 0) red1[f >> 5] = s;
    __syncthreads();
    float mean = (red1[0] + red1[1] + red1[2] + red1[3]) * (1.0f / FF);
    float c = v - mean;
    float s2 = c * c;
    #pragma unroll
    for (int o = 16; o > 0; o >>= 1) s2 += __shfl_xor_sync(0xffffffffu, s2, o);
    if ((f & 31) == 0) red2[f >> 5] = s2;
    __syncthreads();
    float var = (red2[0] + red2[1] + red2[2] + red2[3]) * (1.0f / FF);
    float y = c * rsqrtf(var + 1e-5f) * w[f] + b[f];
    __nv_bfloat16 hi = __float2bfloat16(y);
    __nv_bfloat16 lo = __float2bfloat16(y - __bfloat162float(hi));
    g_xn2[(size_t)n * KP128 + f] = hi;
    g_xn2[(size_t)n * KP128 + 128 + f] = lo;
    g_xn2[(size_t)n * KP128 + 256 + f] = hi;
}

// ---------------- counting sort by dst ----------------
__global__ void hist_kernel(const int* __restrict__ ei) {
    int i = blockIdx.x * blockDim.x + threadIdx.x;
    if (i < EE) atomicAdd(&g_hist[ei[EE + i]], 1);
}
__global__ __launch_bounds__(1024) void scan_kernel() {
    __shared__ int wsum[32];
    __shared__ int carry;
    int tid = threadIdx.x, lane = tid & 31, wid = tid >> 5;
    if (tid == 0) carry = 0;
    __syncthreads();
    for (int c = 0; c < NN; c += 1024) {
        int idx = c + tid;
        int v = (idx < NN) ? g_hist[idx] : 0;
        int x = v;
        #pragma unroll
        for (int o = 1; o < 32; o <<= 1) {
            int t = __shfl_up_sync(0xffffffffu, x, o);
            if (lane >= o) x += t;
        }
        if (lane == 31) wsum[wid] = x;
        __syncthreads();
        if (wid == 0) {
            int s = wsum[lane];
            #pragma unroll
            for (int o = 1; o < 32; o <<= 1) {
                int t = __shfl_up_sync(0xffffffffu, s, o);
                if (lane >= o) s += t;
            }
            wsum[lane] = s;
        }
        __syncthreads();
        int excl = carry + (wid ? wsum[wid - 1] : 0) + x - v;
        if (idx < NN) g_cursor[idx] = excl;
        __syncthreads();
        if (tid == 0) carry += wsum[31];
        __syncthreads();
    }
}
__global__ void scatter_kernel(const int* __restrict__ ei) {
    int i = blockIdx.x * blockDim.x + threadIdx.x;
    if (i >= EE) return;
    int d = ei[EE + i];
    int pos = atomicAdd(&g_cursor[d], 1);
    g_perm[pos] = i;
}

// ---------------- HMMA bf16 GEMM v6: 2x2 warps, 64x64 warp tile (smem traffic cut) ---
#define SPITCH 40
#define STAGE_BYTES (128 * SPITCH * 2)
#define HMMA_SMEM (3 * 2 * STAGE_BYTES)

__global__ __launch_bounds__(128) void hmma_gemm(
    const __nv_bfloat16* __restrict__ A2, const __nv_bfloat16* __restrict__ B2,
    const float* __restrict__ bias, float* __restrict__ C, int M, int Nn, int act,
    int nkt) {
    extern __shared__ char dynsmem[];

    int tid = threadIdx.x;
    int wid = tid >> 5, lane = tid & 31;
    int wm = wid & 1, wn = wid >> 1;          // 2m x 2n warp grid, 64x64 warp tile
    int row0 = blockIdx.y * 128;
    int col0 = blockIdx.x * 128;
    size_t KP = (size_t)nkt * 32;

    uint32_t sA_base[3], sB_base[3];
    #pragma unroll
    for (int s = 0; s < 3; s++) {
        sA_base[s] = smem_u32(dynsmem + s * 2 * STAGE_BYTES);
        sB_base[s] = sA_base[s] + STAGE_BYTES;
    }

    float acc[4][8][4];
    #pragma unroll
    for (int i = 0; i < 4; i++)
        #pragma unroll
        for (int j = 0; j < 8; j++)
            #pragma unroll
            for (int k = 0; k < 4; k++) acc[i][j][k] = 0.f;

    auto prefetch = [&](int kt) {
        int buf = kt % 3;
        int off = kt * 32;
        #pragma unroll
        for (int i = 0; i < 4; i++) {
            int idx = tid + i * 128;       // 0..511
            int r = idx >> 2;
            int ch = idx & 3;
            uint32_t soff = (uint32_t)(r * SPITCH + ch * 8) * 2;
            uint32_t valid = (row0 + r < M) ? 16u : 0u;
            cp_async16(sA_base[buf] + soff,
                       A2 + (size_t)(row0 + r) * KP + off + ch * 8, valid);
            cp_async16(sB_base[buf] + soff,
                       B2 + (size_t)(col0 + r) * KP + off + ch * 8, 16u);
        }
        CP_COMMIT();
    };

    prefetch(0);
    prefetch(1);
    #pragma unroll 1
    for (int kt = 0; kt < nkt; kt++) {
        CP_WAIT1();
        __syncthreads();
        if (kt + 2 < nkt) prefetch(kt + 2);
        else CP_COMMIT();
        int buf = kt % 3;
        #pragma unroll
        for (int ks = 0; ks < 32; ks += 16) {
            uint32_t a[4][4], b[8][2];
            #pragma unroll
            for (int mi = 0; mi < 4; mi++) {
                int r = wm * 64 + mi * 16 + (lane & 15);
                int c = ks + (lane >> 4) * 8;
                ldm_x4(a[mi][0], a[mi][1], a[mi][2], a[mi][3],
                       sA_base[buf] + (uint32_t)(r * SPITCH + c) * 2);
            }
            #pragma unroll
            for (int nip = 0; nip < 4; nip++) {   // covers ni = 2*nip, 2*nip+1
                int m = lane >> 3;
                int r = wn * 64 + nip * 16 + (m >> 1) * 8 + (lane & 7);
                int c = ks + (m & 1) * 8;
                ldm_x4(b[2 * nip][0], b[2 * nip][1], b[2 * nip + 1][0], b[2 * nip + 1][1],
                       sB_base[buf] + (uint32_t)(r * SPITCH + c) * 2);
            }
            #pragma unroll
            for (int mi = 0; mi < 4; mi++)
                #pragma unroll
                for (int ni = 0; ni < 8; ni++)
                    mma_bf16(acc[mi][ni], a[mi], b[ni]);
        }
    }

    #pragma unroll
    for (int ni = 0; ni < 8; ni++) {
        int n = col0 + wn * 64 + ni * 8 + (lane & 3) * 2;
        float b0 = bias[n], b1 = bias[n + 1];
        #pragma unroll
        for (int mi = 0; mi < 4; mi++) {
            int m = row0 + wm * 64 + mi * 16 + (lane >> 2);
            float v0 = acc[mi][ni][0] + b0;
            float v1 = acc[mi][ni][1] + b1;
            float v2 = acc[mi][ni][2] + b0;
            float v3 = acc[mi][ni][3] + b1;
            if (act) {
                v0 = v0 / (1.f + __expf(-v0));
                v1 = v1 / (1.f + __expf(-v1));
                v2 = v2 / (1.f + __expf(-v2));
                v3 = v3 / (1.f + __expf(-v3));
            }
            if (m < M)     *(float2*)(C + (size_t)m * Nn + n)       = make_float2(v0, v1);
            if (m + 8 < M) *(float2*)(C + (size_t)(m + 8) * Nn + n) = make_float2(v2, v3);
        }
    }
}

// ---------------- edge kernel v5b: dst-sorted, register accumulation, CHUNK=4 --------
#define CHUNK 4
__global__ __launch_bounds__(256) void edge_kernel(const int* __restrict__ ei,
                                                   const float* __restrict__ r_ij,
                                                   const float* __restrict__ d_ij,
                                                   const float* __restrict__ vec) {
    int gw = (blockIdx.x * blockDim.x + threadIdx.x) >> 5;
    int lane = threadIdx.x & 31;
    size_t base = (size_t)gw * CHUNK;
    if (base >= EE) return;
    int nmax = (int)(((size_t)EE - base) < CHUNK ? (EE - base) : CHUNK);

    int eL = 0, srcL = 0, dstL = -1;
    float rL = 0.f, dxL = 0.f, dyL = 0.f, dzL = 0.f;
    if (lane < nmax) {
        eL = g_perm[base + lane];
        srcL = ei[eL];
        dstL = ei[EE + eL];
        rL = r_ij[eL];
        dxL = d_ij[(size_t)eL * 3 + 0];
        dyL = d_ij[(size_t)eL * 3 + 1];
        dzL = d_ij[(size_t)eL * 3 + 2];
    }

    int h = lane >> 2;
    int d4 = (lane & 3) * 4;
    int prev = -1;
    float4 q = make_float4(0.f, 0.f, 0.f, 0.f);
    float4 ax  = make_float4(0.f, 0.f, 0.f, 0.f);
    float4 av0 = ax, av1 = ax, av2 = ax;

    for (int i = 0; i < nmax; i++) {
        int e   = __shfl_sync(0xffffffffu, eL, i);
        int src = __shfl_sync(0xffffffffu, srcL, i);
        int dst = __shfl_sync(0xffffffffu, dstL, i);
        if (dst != prev) {
            if (prev >= 0) {
                red_add_v4(g_xagg + (size_t)prev * FF + lane * 4, ax);
                red_add_v4(g_vagg + (size_t)prev * 384 +       lane * 4, av0);
                red_add_v4(g_vagg + (size_t)prev * 384 + 128 + lane * 4, av1);
                red_add_v4(g_vagg + (size_t)prev * 384 + 256 + lane * 4, av2);
            }
            ax = av0 = av1 = av2 = make_float4(0.f, 0.f, 0.f, 0.f);
            q = ((const float4*)(g_qkv + (size_t)dst * 640))[lane];
            prev = dst;
        }
        float4 kk = ((const float4*)(g_qkv + (size_t)src * 640 + 128))[lane];
        float4 dk = ((const float4*)(g_dkdv + (size_t)e * 512))[lane];
        float p = q.x * kk.x * dk.x + q.y * kk.y * dk.y + q.z * kk.z * dk.z + q.w * kk.w * dk.w;
        p += __shfl_xor_sync(0xffffffffu, p, 1);
        p += __shfl_xor_sync(0xffffffffu, p, 2);
        float attn = p / (1.f + __expf(-p));
        float r = __shfl_sync(0xffffffffu, rL, i);
        float cut = (r < 6.0f) ? 0.5f * (__cosf(r * 0.52359877559829887f) + 1.f) : 0.f;
        attn *= cut;

        const float* vb  = g_qkv  + (size_t)src * 640 + 256 + h * 48 + d4;
        const float* dvb = g_dkdv + (size_t)e * 512 + 128 + h * 48 + d4;
        float4 v0 = *(const float4*)vb;
        float4 v1 = *(const float4*)(vb + 16);
        float4 v2 = *(const float4*)(vb + 32);
        float4 w0 = *(const float4*)dvb;
        float4 w1 = *(const float4*)(dvb + 16);
        float4 w2 = *(const float4*)(dvb + 32);

        ax.x += v0.x * w0.x * attn; ax.y += v0.y * w0.y * attn;
        ax.z += v0.z * w0.z * attn; ax.w += v0.w * w0.w * attn;
        float4 v1m = make_float4(v1.x * w1.x, v1.y * w1.y, v1.z * w1.z, v1.w * w1.w);
        float4 v2m = make_float4(v2.x * w2.x, v2.y * w2.y, v2.z * w2.z, v2.w * w2.w);

        float dsx = __shfl_sync(0xffffffffu, dxL, i);
        float dsy = __shfl_sync(0xffffffffu, dyL, i);
        float dsz = __shfl_sync(0xffffffffu, dzL, i);
        float4 vv0 = ((const float4*)(vec + (size_t)src * 384))[lane];
        float4 vv1 = ((const float4*)(vec + (size_t)src * 384 + 128))[lane];
        float4 vv2 = ((const float4*)(vec + (size_t)src * 384 + 256))[lane];
        av0.x += vv0.x * v1m.x + v2m.x * dsx; av0.y += vv0.y * v1m.y + v2m.y * dsx;
        av0.z += vv0.z * v1m.z + v2m.z * dsx; av0.w += vv0.w * v1m.w + v2m.w * dsx;
        av1.x += vv1.x * v1m.x + v2m.x * dsy; av1.y += vv1.y * v1m.y + v2m.y * dsy;
        av1.z += vv1.z * v1m.z + v2m.z * dsy; av1.w += vv1.w * v1m.w + v2m.w * dsy;
        av2.x += vv2.x * v1m.x + v2m.x * dsz; av2.y += vv2.y * v1m.y + v2m.y * dsz;
        av2.z += vv2.z * v1m.z + v2m.z * dsz; av2.w += vv2.w * v1m.w + v2m.w * dsz;
    }
    if (prev >= 0) {
        red_add_v4(g_xagg + (size_t)prev * FF + lane * 4, ax);
        red_add_v4(g_vagg + (size_t)prev * 384 +       lane * 4, av0);
        red_add_v4(g_vagg + (size_t)prev * 384 + 128 + lane * 4, av1);
        red_add_v4(g_vagg + (size_t)prev * 384 + 256 + lane * 4, av2);
    }
}

// ---------------- final epilogue ----------------
__global__ void final_kernel(float* __restrict__ out) {
    int n = blockIdx.x;
    int f = threadIdx.x;  // 128
    size_t ob = (size_t)n * 384;
    float o1 = g_o[ob + f], o2 = g_o[ob + 128 + f], o3 = g_o[ob + 256 + f];
    size_t vb = (size_t)n * 1152;
    float vd = 0.f;
    #pragma unroll
    for (int s = 0; s < 3; s++)
        vd += g_vp[vb + s * 384 + f] * g_vp[vb + s * 384 + 128 + f];
    out[(size_t)n * FF + f] = vd * o2 + o3;
    #pragma unroll
    for (int s = 0; s < 3; s++) {
        float v3 = g_vp[vb + s * 384 + 256 + f];
        out[(size_t)NN * FF + ((size_t)n * 3 + s) * FF + f] =
            v3 * o1 + g_vagg[((size_t)n * 3 + s) * FF + f];
    }
}

// ---------------- launch: multi-stream overlap (r15 topology) ----------------
extern "C" void kernel_launch(void* const* d_in, const int* in_sizes, int n_in,
                              void* d_out, int out_size) {
    const float* x    = (const float*)d_in[0];
    const float* vec  = (const float*)d_in[1];
    const int*   ei   = (const int*)d_in[2];
    const float* r_ij = (const float*)d_in[3];
    const float* f_ij = (const float*)d_in[4];
    const float* d_ij = (const float*)d_in[5];
    const float* ln_w = (const float*)d_in[6];
    const float* ln_b = (const float*)d_in[7];
    const float* Wq   = (const float*)d_in[8];
    const float* bq   = (const float*)d_in[9];
    const float* Wk   = (const float*)d_in[10];
    const float* bk   = (const float*)d_in[11];
    const float* Wv   = (const float*)d_in[12];
    const float* bv   = (const float*)d_in[13];
    const float* Wvec = (const float*)d_in[14];
    const float* bvec = (const float*)d_in[15];
    const float* Wo   = (const float*)d_in[16];
    const float* bo   = (const float*)d_in[17];
    const float* Wdk  = (const float*)d_in[18];
    const float* bdk  = (const float*)d_in[19];
    const float* Wdv  = (const float*)d_in[20];
    const float* bdv  = (const float*)d_in[21];
    float* out = (float*)d_out;

    void *pqkv, *pvp, *pdkdv, *pxagg, *pvagg, *po, *pbqkv, *pbdkv, *phist;
    void *pxn2, *pvec2, *pfij2, *pxagg2, *pWqkv2, *pWvec2, *pWdkv2, *pWo2;
    cudaGetSymbolAddress(&pqkv, g_qkv);
    cudaGetSymbolAddress(&pvp, g_vp);
    cudaGetSymbolAddress(&pdkdv, g_dkdv);
    cudaGetSymbolAddress(&pxagg, g_xagg);
    cudaGetSymbolAddress(&pvagg, g_vagg);
    cudaGetSymbolAddress(&po, g_o);
    cudaGetSymbolAddress(&pbqkv, g_bqkv);
    cudaGetSymbolAddress(&pbdkv, g_bdkv);
    cudaGetSymbolAddress(&phist, g_hist);
    cudaGetSymbolAddress(&pxn2, g_xn2);
    cudaGetSymbolAddress(&pvec2, g_vec2);
    cudaGetSymbolAddress(&pfij2, g_fij2);
    cudaGetSymbolAddress(&pxagg2, g_xagg2);
    cudaGetSymbolAddress(&pWqkv2, g_Wqkv2);
    cudaGetSymbolAddress(&pWvec2, g_Wvec2);
    cudaGetSymbolAddress(&pWdkv2, g_Wdkv2);
    cudaGetSymbolAddress(&pWo2, g_Wo2);

    cudaFuncSetAttribute(hmma_gemm, cudaFuncAttributeMaxDynamicSharedMemorySize, HMMA_SMEM);

    static cudaStream_t s1 = nullptr, s2 = nullptr;
    static cudaEvent_t ev0 = nullptr, evW = nullptr, evQ = nullptr, evS = nullptr,
                       evV = nullptr;
    if (!s1) {
        cudaStreamCreateWithFlags(&s1, cudaStreamNonBlocking);
        cudaStreamCreateWithFlags(&s2, cudaStreamNonBlocking);
        cudaEventCreateWithFlags(&ev0, cudaEventDisableTiming);
        cudaEventCreateWithFlags(&evW, cudaEventDisableTiming);
        cudaEventCreateWithFlags(&evQ, cudaEventDisableTiming);
        cudaEventCreateWithFlags(&evS, cudaEventDisableTiming);
        cudaEventCreateWithFlags(&evV, cudaEventDisableTiming);
    }
    cudaStream_t s0 = 0;  // capture-origin stream

    // ---- fork at capture start ----
    cudaEventRecord(ev0, s0);

    // ---- s0 (critical path): cvt100 -> (weights ready) dkdv GEMM ----
    cvt100<<<(EE * 32 + 255) / 256, 256, 0, s0>>>(f_ij, (__nv_bfloat16*)pfij2, EE);
    // ---- s1 (forked): prep -> ln -> qkv GEMM ; cvt(vec) -> vp GEMM ----
    cudaStreamWaitEvent(s1, ev0, 0);
    prep_all<<<(640 * 128 + 255) / 256, 256, 0, s1>>>(Wq, Wk, Wv, bq, bk, bv,
                                                      Wdk, Wdv, bdk, bdv, Wvec, Wo);
    cudaEventRecord(evW, s1);                       // weights ready
    ln_kernel<<<NN, 128, 0, s1>>>(x, ln_w, ln_b);
    {
        dim3 grid(640 / 128, (NN + 127) / 128);
        hmma_gemm<<<grid, 128, HMMA_SMEM, s1>>>((const __nv_bfloat16*)pxn2,
                                                (const __nv_bfloat16*)pWqkv2,
                                                (const float*)pbqkv, (float*)pqkv,
                                                NN, 640, 0, 12);
    }
    cudaEventRecord(evQ, s1);                       // qkv ready (for edge)
    cvt128<<<(3 * NN * 32 + 255) / 256, 256, 0, s1>>>(vec, (__nv_bfloat16*)pvec2, 3 * NN);
    {
        dim3 grid(384 / 128, (3 * NN + 127) / 128);
        hmma_gemm<<<grid, 128, HMMA_SMEM, s1>>>((const __nv_bfloat16*)pvec2,
                                                (const __nv_bfloat16*)pWvec2,
                                                bvec, (float*)pvp, 3 * NN, 384, 0, 12);
    }
    cudaEventRecord(evV, s1);                       // vp ready (for final)

    // ---- s2 (forked): counting sort + agg zeroing ----
    cudaStreamWaitEvent(s2, ev0, 0);
    cudaMemsetAsync(phist, 0, NN * sizeof(int), s2);
    hist_kernel<<<(EE + 255) / 256, 256, 0, s2>>>(ei);
    scan_kernel<<<1, 1024, 0, s2>>>();
    scatter_kernel<<<(EE + 255) / 256, 256, 0, s2>>>(ei);
    cudaMemsetAsync(pxagg, 0, (size_t)NN * FF * sizeof(float), s2);
    cudaMemsetAsync(pvagg, 0, (size_t)NN * 384 * sizeof(float), s2);
    cudaEventRecord(evS, s2);                       // sort + zeroed aggs ready

    // ---- s0: dkdv GEMM (after weights) [10 k-tiles] ----
    cudaStreamWaitEvent(s0, evW, 0);
    {
        dim3 grid(512 / 128, EE / 128);
        hmma_gemm<<<grid, 128, HMMA_SMEM, s0>>>((const __nv_bfloat16*)pfij2,
                                                (const __nv_bfloat16*)pWdkv2,
                                                (const float*)pbdkv, (float*)pdkdv,
                                                EE, 512, 1, 10);
    }

    // ---- s0 join: edge -> cvt(xagg) -> o GEMM -> (join vp) final ----
    cudaStreamWaitEvent(s0, evQ, 0);
    cudaStreamWaitEvent(s0, evS, 0);
    {
        int warps = (EE + CHUNK - 1) / CHUNK;
        edge_kernel<<<(warps * 32 + 255) / 256, 256, 0, s0>>>(ei, r_ij, d_ij, vec);
    }
    cvt128<<<(NN * 32 + 255) / 256, 256, 0, s0>>>((const float*)pxagg,
                                                  (__nv_bfloat16*)pxagg2, NN);
    {
        dim3 grid(384 / 128, (NN + 127) / 128);
        hmma_gemm<<<grid, 128, HMMA_SMEM, s0>>>((const __nv_bfloat16*)pxagg2,
                                                (const __nv_bfloat16*)pWo2,
                                                bo, (float*)po, NN, 384, 0, 12);
    }
    cudaStreamWaitEvent(s0, evV, 0);
    final_kernel<<<NN, 128, 0, s0>>>(out);
}